// round 4
// baseline (speedup 1.0000x reference)
#include <cuda_runtime.h>
#include <cstdint>
#include <cstddef>

// ---------------------------------------------------------------------------
// out = fq(x) @ fq(W)^T + bias, fq = per-tensor symmetric int8 fake quant.
// x[16384,4096] fp32, W[4096,4096] fp32, bias[4096] -> out[16384,4096] fp32.
//
// Exact decomposition: fq(t) = q_t * s_t with q_t integer int8 and
// s_t = max(amax_t/127, 1e-8). So out = (q_x @ q_w^T) * (s_x*s_w) + bias,
// computed exactly with int8 mma.sync (s32 accumulation).
// NOTE: tcgen05 unusable (harness PTX targets sm_103, not sm_103a) -> IMMA.
// R3 fix: never pass __device__ array symbols as kernel args from host;
// quant kernels now reference g_qx/g_qw directly in device code.
// ---------------------------------------------------------------------------

#define MT 16384
#define NT 4096
#define KT 4096

__device__ __align__(1024) int8_t g_qx[(size_t)MT * KT]; // 64 MiB scratch
__device__ __align__(1024) int8_t g_qw[(size_t)NT * KT]; // 16 MiB scratch
__device__ unsigned g_amax_x;
__device__ unsigned g_amax_w;

__device__ __forceinline__ uint32_t smem_to_u32(const void* smem_ptr) {
    uint32_t addr;
    asm("{ .reg .u64 tmp; cvta.to.shared.u64 tmp, %1; cvt.u32.u64 %0, tmp; }"
        : "=r"(addr) : "l"(smem_ptr));
    return addr;
}

// ---------------------------------------------------------------------------
// Pass 0: reset reduction state (graph replays must be deterministic)
// ---------------------------------------------------------------------------
__global__ void init_kernel() {
    if (threadIdx.x == 0) { g_amax_x = 0u; g_amax_w = 0u; }
}

// ---------------------------------------------------------------------------
// Pass 1: abs-max (float bits of nonneg floats order like uints)
// ---------------------------------------------------------------------------
__global__ void amax_kernel(const float* __restrict__ p, int n4, int sel) {
    __shared__ float red[8];
    float m = 0.f;
    const float4* p4 = (const float4*)p;
    int stride = gridDim.x * blockDim.x;
    for (int i = blockIdx.x * blockDim.x + threadIdx.x; i < n4; i += stride) {
        float4 v = p4[i];
        m = fmaxf(m, fmaxf(fmaxf(fabsf(v.x), fabsf(v.y)),
                           fmaxf(fabsf(v.z), fabsf(v.w))));
    }
    #pragma unroll
    for (int o = 16; o; o >>= 1) m = fmaxf(m, __shfl_xor_sync(0xffffffffu, m, o));
    if ((threadIdx.x & 31) == 0) red[threadIdx.x >> 5] = m;
    __syncthreads();
    if (threadIdx.x == 0) {
        float mm = red[0];
        for (int j = 1; j < (int)(blockDim.x >> 5); j++) mm = fmaxf(mm, red[j]);
        atomicMax(sel ? &g_amax_w : &g_amax_x, __float_as_uint(mm));
    }
}

// ---------------------------------------------------------------------------
// Pass 2: quantize fp32 -> int8 (round-half-even like jnp.round, clip +-127).
// Destination selected in DEVICE code (device-symbol addresses are only valid
// device-side).
// ---------------------------------------------------------------------------
__device__ __forceinline__ int q1(float v, float inv_scale) {
    int q = __float2int_rn(v * inv_scale);   // round-to-nearest-even
    return max(-127, min(127, q));
}

__global__ void quant_kernel(const float* __restrict__ in, int n4, int sel) {
    float scale = fmaxf(__uint_as_float(sel ? g_amax_w : g_amax_x) * (1.f / 127.f),
                        1e-8f);
    float inv = 1.f / scale;
    const float4* in4 = (const float4*)in;
    uint32_t* o4 = sel ? (uint32_t*)g_qw : (uint32_t*)g_qx;
    int stride = gridDim.x * blockDim.x;
    for (int i = blockIdx.x * blockDim.x + threadIdx.x; i < n4; i += stride) {
        float4 v = in4[i];
        uint32_t w = (uint32_t)(q1(v.x, inv) & 0xff)
                   | ((uint32_t)(q1(v.y, inv) & 0xff) << 8)
                   | ((uint32_t)(q1(v.z, inv) & 0xff) << 16)
                   | ((uint32_t)(q1(v.w, inv) & 0xff) << 24);
        o4[i] = w;
    }
}

// ---------------------------------------------------------------------------
// Pass 3: int8 GEMM. Tile 128x128x64, 256 threads (2x4 warps, 64x32 / warp),
// 4-stage cp.async pipeline, ldmatrix fragment loads, mma.m16n8k32.s8.
// ---------------------------------------------------------------------------
#define BM 128
#define BN 128
#define BK 64
#define STAGES 4
#define NITER (KT / BK)                 // 64
#define ASZ (BM * BK)                   // 8192 B
#define BSZ (BN * BK)                   // 8192 B
#define STAGE_BYTES (ASZ + BSZ)         // 16384 B
#define GEMM_SMEM (STAGES * STAGE_BYTES) // 65536 B

// 64-byte rows, 4 x 16B chunks; chunk' = chunk ^ ((row>>1)&3) is conflict-free
// both for 16B cp.async stores and for ldmatrix (8 lanes x 16B distinct mod 128B).
__device__ __forceinline__ uint32_t swz(uint32_t row, uint32_t c) {
    return row * 64u + ((c ^ ((row >> 1) & 3u)) << 4);
}

#define CP16(dst, src) \
    asm volatile("cp.async.cg.shared.global [%0], [%1], 16;" :: "r"(dst), "l"(src))
#define CP_COMMIT() asm volatile("cp.async.commit_group;" ::: "memory")
#define CP_WAIT(n)  asm volatile("cp.async.wait_group %0;" :: "n"(n) : "memory")

#define LDSM_X4(r0, r1, r2, r3, a) \
    asm volatile("ldmatrix.sync.aligned.m8n8.x4.shared.b16 {%0,%1,%2,%3}, [%4];" \
        : "=r"(r0), "=r"(r1), "=r"(r2), "=r"(r3) : "r"(a))

#define MMA_S8(c, a, b0, b1) \
    asm volatile("mma.sync.aligned.m16n8k32.row.col.s32.s8.s8.s32 " \
        "{%0,%1,%2,%3}, {%4,%5,%6,%7}, {%8,%9}, {%0,%1,%2,%3};" \
        : "+r"((c)[0]), "+r"((c)[1]), "+r"((c)[2]), "+r"((c)[3]) \
        : "r"((a)[0]), "r"((a)[1]), "r"((a)[2]), "r"((a)[3]), "r"(b0), "r"(b1))

__device__ __forceinline__ void load_stage(uint32_t sbase, const int8_t* Ab,
                                           const int8_t* Bb, int kc, int tid) {
    #pragma unroll
    for (int it = 0; it < 4; it++) {
        int u = tid + it * 256;           // 0..1023
        int cu = u & 511;
        int row = cu >> 2;
        int c = cu & 3;
        const int8_t* g = ((u < 512) ? Ab : Bb)
                        + (size_t)row * KT + kc * BK + c * 16;
        uint32_t dst = sbase + ((u < 512) ? 0u : (uint32_t)ASZ) + swz(row, c);
        CP16(dst, g);
    }
}

__global__ void __launch_bounds__(256, 2)
gemm_kernel(float* __restrict__ out, const float* __restrict__ bias) {
    extern __shared__ char smem[];
    uint32_t sb = smem_to_u32(smem);
    int tid = threadIdx.x, lane = tid & 31, w = tid >> 5;
    int wm = w & 1, wn = w >> 1;          // 2 x 4 warp grid
    int mtile = blockIdx.y, ntile = blockIdx.x;

    const int8_t* Ab = g_qx + (size_t)(mtile * BM) * KT;
    const int8_t* Bb = g_qw + (size_t)(ntile * BN) * KT;

    int acc[4][4][4];
    #pragma unroll
    for (int i = 0; i < 4; i++)
        #pragma unroll
        for (int j = 0; j < 4; j++)
            #pragma unroll
            for (int k = 0; k < 4; k++) acc[i][j][k] = 0;

    // ldmatrix per-lane offsets (relative to stage A/B base), ks=0.
    // ks=1 toggles chunk bit1 -> offset XOR 32 (swizzle commutes with the XOR).
    uint32_t a_row = (uint32_t)(wm * 64 + ((lane >> 3) & 1) * 8 + (lane & 7));
    uint32_t a_cb  = (uint32_t)((lane >> 4) & 1);
    uint32_t aoff[4];
    #pragma unroll
    for (int mt = 0; mt < 4; mt++) aoff[mt] = swz(a_row + mt * 16, a_cb);

    uint32_t b_row = (uint32_t)(wn * 32 + ((lane >> 4) & 1) * 8 + (lane & 7));
    uint32_t b_cb  = (uint32_t)((lane >> 3) & 1);
    uint32_t boff[2];
    #pragma unroll
    for (int p = 0; p < 2; p++) boff[p] = swz(b_row + p * 16, b_cb);

    // Prologue: stages 0..STAGES-2
    #pragma unroll
    for (int s = 0; s < STAGES - 1; s++) {
        load_stage(sb + s * STAGE_BYTES, Ab, Bb, s, tid);
        CP_COMMIT();
    }

    for (int kc = 0; kc < NITER; kc++) {
        CP_WAIT(STAGES - 2);
        __syncthreads();   // stage kc%S ready; everyone done with stage (kc-1)%S

        int lc = kc + STAGES - 1;
        if (lc < NITER)
            load_stage(sb + (lc % STAGES) * STAGE_BYTES, Ab, Bb, lc, tid);
        CP_COMMIT();       // commit every iter (empty at tail) for uniform count

        uint32_t sA = sb + (uint32_t)(kc % STAGES) * STAGE_BYTES;
        uint32_t sB = sA + ASZ;

        #pragma unroll
        for (int ks = 0; ks < 2; ks++) {
            uint32_t x = ks ? 32u : 0u;
            uint32_t a[4][4], bf[2][4];
            #pragma unroll
            for (int mt = 0; mt < 4; mt++)
                LDSM_X4(a[mt][0], a[mt][1], a[mt][2], a[mt][3],
                        sA + (aoff[mt] ^ x));
            #pragma unroll
            for (int p = 0; p < 2; p++)
                LDSM_X4(bf[p][0], bf[p][1], bf[p][2], bf[p][3],
                        sB + (boff[p] ^ x));
            #pragma unroll
            for (int mt = 0; mt < 4; mt++)
                #pragma unroll
                for (int nt = 0; nt < 4; nt++)
                    MMA_S8(acc[mt][nt], a[mt],
                           bf[nt >> 1][(nt & 1) * 2], bf[nt >> 1][(nt & 1) * 2 + 1]);
        }
    }

    // Epilogue: float(acc) * (sx*sw) + bias
    float sx = fmaxf(__uint_as_float(g_amax_x) * (1.f / 127.f), 1e-8f);
    float sw = fmaxf(__uint_as_float(g_amax_w) * (1.f / 127.f), 1e-8f);
    float sc = sx * sw;

    int colbase = ntile * BN + wn * 32 + 2 * (lane & 3);
    int rowbase = mtile * BM + wm * 64 + (lane >> 2);

    float2 bv[4];
    #pragma unroll
    for (int nt = 0; nt < 4; nt++)
        bv[nt] = *reinterpret_cast<const float2*>(bias + colbase + nt * 8);

    #pragma unroll
    for (int mt = 0; mt < 4; mt++) {
        int r = rowbase + mt * 16;
        #pragma unroll
        for (int nt = 0; nt < 4; nt++) {
            int col = colbase + nt * 8;
            float2 v0, v1;
            v0.x = fmaf((float)acc[mt][nt][0], sc, bv[nt].x);
            v0.y = fmaf((float)acc[mt][nt][1], sc, bv[nt].y);
            v1.x = fmaf((float)acc[mt][nt][2], sc, bv[nt].x);
            v1.y = fmaf((float)acc[mt][nt][3], sc, bv[nt].y);
            *reinterpret_cast<float2*>(out + (size_t)r * NT + col) = v0;
            *reinterpret_cast<float2*>(out + (size_t)(r + 8) * NT + col) = v1;
        }
    }
}

// ---------------------------------------------------------------------------
// Launch (graph-capturable; no allocation, no sync)
// ---------------------------------------------------------------------------
extern "C" void kernel_launch(void* const* d_in, const int* in_sizes, int n_in,
                              void* d_out, int out_size) {
    const float* x = (const float*)d_in[0];
    const float* w = (const float*)d_in[1];
    const float* bias = (const float*)d_in[2];
    float* out = (float*)d_out;

    init_kernel<<<1, 32>>>();
    amax_kernel<<<2048, 256>>>(x, (MT * KT) / 4, 0);
    amax_kernel<<<512, 256>>>(w, (NT * KT) / 4, 1);
    quant_kernel<<<4096, 256>>>(x, (MT * KT) / 4, 0);
    quant_kernel<<<1024, 256>>>(w, (NT * KT) / 4, 1);

    cudaFuncSetAttribute(gemm_kernel,
                         cudaFuncAttributeMaxDynamicSharedMemorySize, GEMM_SMEM);
    gemm_kernel<<<dim3(NT / BN, MT / BM), 256, GEMM_SMEM>>>(out, bias);
}

// round 5
// speedup vs baseline: 1.0051x; 1.0051x over previous
#include <cuda_runtime.h>
#include <cstdint>
#include <cstddef>

// ---------------------------------------------------------------------------
// out = fq(x) @ fq(W)^T + bias, fq = per-tensor symmetric int8 fake quant.
// Exact: out = (q_x @ q_w^T) * (s_x*s_w) + bias via int8 mma.sync (s32 acc).
// R4: BK 64->128 (halve barriers), strength-reduced cp.async addressing.
// ---------------------------------------------------------------------------

#define MT 16384
#define NT 4096
#define KT 4096

__device__ __align__(1024) int8_t g_qx[(size_t)MT * KT]; // 64 MiB scratch
__device__ __align__(1024) int8_t g_qw[(size_t)NT * KT]; // 16 MiB scratch
__device__ unsigned g_amax_x;
__device__ unsigned g_amax_w;

__device__ __forceinline__ uint32_t smem_to_u32(const void* smem_ptr) {
    uint32_t addr;
    asm("{ .reg .u64 tmp; cvta.to.shared.u64 tmp, %1; cvt.u32.u64 %0, tmp; }"
        : "=r"(addr) : "l"(smem_ptr));
    return addr;
}

// ---------------------------------------------------------------------------
// Pass 0: reset reduction state (graph replays must be deterministic)
// ---------------------------------------------------------------------------
__global__ void init_kernel() {
    if (threadIdx.x == 0) { g_amax_x = 0u; g_amax_w = 0u; }
}

// ---------------------------------------------------------------------------
// Pass 1: abs-max (float bits of nonneg floats order like uints)
// ---------------------------------------------------------------------------
__global__ void amax_kernel(const float* __restrict__ p, int n4, int sel) {
    __shared__ float red[8];
    float m = 0.f;
    const float4* p4 = (const float4*)p;
    int stride = gridDim.x * blockDim.x;
    for (int i = blockIdx.x * blockDim.x + threadIdx.x; i < n4; i += stride) {
        float4 v = p4[i];
        m = fmaxf(m, fmaxf(fmaxf(fabsf(v.x), fabsf(v.y)),
                           fmaxf(fabsf(v.z), fabsf(v.w))));
    }
    #pragma unroll
    for (int o = 16; o; o >>= 1) m = fmaxf(m, __shfl_xor_sync(0xffffffffu, m, o));
    if ((threadIdx.x & 31) == 0) red[threadIdx.x >> 5] = m;
    __syncthreads();
    if (threadIdx.x == 0) {
        float mm = red[0];
        for (int j = 1; j < (int)(blockDim.x >> 5); j++) mm = fmaxf(mm, red[j]);
        atomicMax(sel ? &g_amax_w : &g_amax_x, __float_as_uint(mm));
    }
}

// ---------------------------------------------------------------------------
// Pass 2: quantize fp32 -> int8 (round-half-even, clip +-127)
// ---------------------------------------------------------------------------
__device__ __forceinline__ int q1(float v, float inv_scale) {
    int q = __float2int_rn(v * inv_scale);
    return max(-127, min(127, q));
}

__global__ void quant_kernel(const float* __restrict__ in, int n4, int sel) {
    float scale = fmaxf(__uint_as_float(sel ? g_amax_w : g_amax_x) * (1.f / 127.f),
                        1e-8f);
    float inv = 1.f / scale;
    const float4* in4 = (const float4*)in;
    uint32_t* o4 = sel ? (uint32_t*)g_qw : (uint32_t*)g_qx;
    int stride = gridDim.x * blockDim.x;
    for (int i = blockIdx.x * blockDim.x + threadIdx.x; i < n4; i += stride) {
        float4 v = in4[i];
        uint32_t w = (uint32_t)(q1(v.x, inv) & 0xff)
                   | ((uint32_t)(q1(v.y, inv) & 0xff) << 8)
                   | ((uint32_t)(q1(v.z, inv) & 0xff) << 16)
                   | ((uint32_t)(q1(v.w, inv) & 0xff) << 24);
        o4[i] = w;
    }
}

// ---------------------------------------------------------------------------
// Pass 3: int8 GEMM. Tile 128x128x128, 256 threads (2x4 warps, 64x32 / warp),
// 3-stage cp.async pipeline (96 KB smem, 2 CTA/SM), mma.m16n8k32.s8.
// ---------------------------------------------------------------------------
#define BM 128
#define BN 128
#define BK 128
#define STAGES 3
#define NITER (KT / BK)                  // 32
#define ASZ (BM * BK)                    // 16384 B
#define BSZ (BN * BK)                    // 16384 B
#define STAGE_BYTES (ASZ + BSZ)          // 32768 B
#define GEMM_SMEM (STAGES * STAGE_BYTES) // 98304 B

// 128B rows, 8 x 16B chunks; chunk' = chunk ^ (row&7): conflict-free for the
// 16B cp.async stores (4 rows x 8 chunks fully cover 4 lines) and for
// ldmatrix (8 rows same chunk -> 8 distinct 16B banks mod 128B).
__device__ __forceinline__ uint32_t swz128(uint32_t row, uint32_t c) {
    return row * 128u + ((c ^ (row & 7u)) << 4);
}

#define CP16(dst, src) \
    asm volatile("cp.async.cg.shared.global [%0], [%1], 16;" :: "r"(dst), "l"(src))
#define CP_COMMIT() asm volatile("cp.async.commit_group;" ::: "memory")
#define CP_WAIT(n)  asm volatile("cp.async.wait_group %0;" :: "n"(n) : "memory")

#define LDSM_X4(r0, r1, r2, r3, a) \
    asm volatile("ldmatrix.sync.aligned.m8n8.x4.shared.b16 {%0,%1,%2,%3}, [%4];" \
        : "=r"(r0), "=r"(r1), "=r"(r2), "=r"(r3) : "r"(a))

#define MMA_S8(c, a, b0, b1) \
    asm volatile("mma.sync.aligned.m16n8k32.row.col.s32.s8.s8.s32 " \
        "{%0,%1,%2,%3}, {%4,%5,%6,%7}, {%8,%9}, {%0,%1,%2,%3};" \
        : "+r"((c)[0]), "+r"((c)[1]), "+r"((c)[2]), "+r"((c)[3]) \
        : "r"((a)[0]), "r"((a)[1]), "r"((a)[2]), "r"((a)[3]), "r"(b0), "r"(b1))

__global__ void __launch_bounds__(256, 2)
gemm_kernel(float* __restrict__ out, const float* __restrict__ bias) {
    extern __shared__ char smem[];
    uint32_t sb = smem_to_u32(smem);
    int tid = threadIdx.x, lane = tid & 31, w = tid >> 5;
    int wm = w & 1, wn = w >> 1;          // 2 x 4 warp grid
    int mtile = blockIdx.y, ntile = blockIdx.x;

    // --- per-thread cp.async constants (strength-reduced) ------------------
    // Thread covers rows {r0, r0+32, r0+64, r0+96}, one 16B chunk cc, for A
    // and the same pattern for B. Global advance per iter = +BK bytes.
    int r0 = tid >> 3, cc = tid & 7;
    const int8_t* gA = g_qx + ((size_t)(mtile * BM + r0)) * KT + cc * 16;
    const int8_t* gB = g_qw + ((size_t)(ntile * BN + r0)) * KT + cc * 16;
    uint32_t dA = swz128((uint32_t)r0, (uint32_t)cc);   // smem offset, stage-rel

    int acc[4][4][4];
    #pragma unroll
    for (int i = 0; i < 4; i++)
        #pragma unroll
        for (int j = 0; j < 4; j++)
            #pragma unroll
            for (int k = 0; k < 4; k++) acc[i][j][k] = 0;

    // ldmatrix per-lane offsets (stage-relative), ks=0. For ks>0 the chunk
    // index gains (ks<<1) in disjoint bits -> offset XORs with (ks<<5).
    uint32_t a_row = (uint32_t)(wm * 64 + ((lane >> 3) & 1) * 8 + (lane & 7));
    uint32_t a_cb  = (uint32_t)((lane >> 4) & 1);
    uint32_t aoff[4];
    #pragma unroll
    for (int mt = 0; mt < 4; mt++) aoff[mt] = swz128(a_row + mt * 16, a_cb);

    uint32_t b_row = (uint32_t)(wn * 32 + ((lane >> 4) & 1) * 8 + (lane & 7));
    uint32_t b_cb  = (uint32_t)((lane >> 3) & 1);
    uint32_t boff[2];
    #pragma unroll
    for (int p = 0; p < 2; p++) boff[p] = swz128(b_row + p * 16, b_cb);

    // --- prologue: stages 0..STAGES-2 --------------------------------------
    #pragma unroll
    for (int s = 0; s < STAGES - 1; s++) {
        uint32_t st = sb + (uint32_t)s * STAGE_BYTES;
        #pragma unroll
        for (int it = 0; it < 4; it++)
            CP16(st + dA + it * 4096u, gA + (size_t)it * 32 * KT + s * BK);
        #pragma unroll
        for (int it = 0; it < 4; it++)
            CP16(st + ASZ + dA + it * 4096u, gB + (size_t)it * 32 * KT + s * BK);
        CP_COMMIT();
    }

    for (int kc = 0; kc < NITER; kc++) {
        CP_WAIT(STAGES - 2);
        __syncthreads();   // stage kc%S ready; all warps done with stage kc-1

        int lc = kc + STAGES - 1;
        if (lc < NITER) {
            uint32_t st = sb + (uint32_t)(lc % STAGES) * STAGE_BYTES;
            #pragma unroll
            for (int it = 0; it < 4; it++)
                CP16(st + dA + it * 4096u, gA + (size_t)it * 32 * KT + lc * BK);
            #pragma unroll
            for (int it = 0; it < 4; it++)
                CP16(st + ASZ + dA + it * 4096u,
                     gB + (size_t)it * 32 * KT + lc * BK);
        }
        CP_COMMIT();       // uniform group count (empty at tail)

        uint32_t sA = sb + (uint32_t)(kc % STAGES) * STAGE_BYTES;
        uint32_t sB = sA + ASZ;

        #pragma unroll
        for (int ks = 0; ks < 4; ks++) {
            uint32_t x = (uint32_t)ks << 5;
            uint32_t a[4][4], bf[2][4];
            #pragma unroll
            for (int mt = 0; mt < 4; mt++)
                LDSM_X4(a[mt][0], a[mt][1], a[mt][2], a[mt][3],
                        sA + (aoff[mt] ^ x));
            #pragma unroll
            for (int p = 0; p < 2; p++)
                LDSM_X4(bf[p][0], bf[p][1], bf[p][2], bf[p][3],
                        sB + (boff[p] ^ x));
            #pragma unroll
            for (int mt = 0; mt < 4; mt++)
                #pragma unroll
                for (int nt = 0; nt < 4; nt++)
                    MMA_S8(acc[mt][nt], a[mt],
                           bf[nt >> 1][(nt & 1) * 2], bf[nt >> 1][(nt & 1) * 2 + 1]);
        }
    }

    // --- epilogue: float(acc) * (sx*sw) + bias -----------------------------
    float sx = fmaxf(__uint_as_float(g_amax_x) * (1.f / 127.f), 1e-8f);
    float sw = fmaxf(__uint_as_float(g_amax_w) * (1.f / 127.f), 1e-8f);
    float sc = sx * sw;

    int colbase = ntile * BN + wn * 32 + 2 * (lane & 3);
    int rowbase = mtile * BM + wm * 64 + (lane >> 2);

    float2 bv[4];
    #pragma unroll
    for (int nt = 0; nt < 4; nt++)
        bv[nt] = *reinterpret_cast<const float2*>(bias + colbase + nt * 8);

    #pragma unroll
    for (int mt = 0; mt < 4; mt++) {
        int r = rowbase + mt * 16;
        #pragma unroll
        for (int nt = 0; nt < 4; nt++) {
            int col = colbase + nt * 8;
            float2 v0, v1;
            v0.x = fmaf((float)acc[mt][nt][0], sc, bv[nt].x);
            v0.y = fmaf((float)acc[mt][nt][1], sc, bv[nt].y);
            v1.x = fmaf((float)acc[mt][nt][2], sc, bv[nt].x);
            v1.y = fmaf((float)acc[mt][nt][3], sc, bv[nt].y);
            *reinterpret_cast<float2*>(out + (size_t)r * NT + col) = v0;
            *reinterpret_cast<float2*>(out + (size_t)(r + 8) * NT + col) = v1;
        }
    }
}

// ---------------------------------------------------------------------------
// Launch (graph-capturable; no allocation, no sync)
// ---------------------------------------------------------------------------
extern "C" void kernel_launch(void* const* d_in, const int* in_sizes, int n_in,
                              void* d_out, int out_size) {
    const float* x = (const float*)d_in[0];
    const float* w = (const float*)d_in[1];
    const float* bias = (const float*)d_in[2];
    float* out = (float*)d_out;

    init_kernel<<<1, 32>>>();
    amax_kernel<<<2048, 256>>>(x, (MT * KT) / 4, 0);
    amax_kernel<<<512, 256>>>(w, (NT * KT) / 4, 1);
    quant_kernel<<<4096, 256>>>(x, (MT * KT) / 4, 0);
    quant_kernel<<<1024, 256>>>(w, (NT * KT) / 4, 1);

    cudaFuncSetAttribute(gemm_kernel,
                         cudaFuncAttributeMaxDynamicSharedMemorySize, GEMM_SMEM);
    gemm_kernel<<<dim3(NT / BN, MT / BM), 256, GEMM_SMEM>>>(out, bias);
}

// round 7
// speedup vs baseline: 1.0094x; 1.0042x over previous
#include <cuda_runtime.h>
#include <cstdint>
#include <cstddef>

// ---------------------------------------------------------------------------
// out = fq(x) @ fq(W)^T + bias, fq = per-tensor symmetric int8 fake quant.
// Exact: out = (q_x @ q_w^T) * (s_x*s_w) + bias via int8 mma.sync (s32 acc).
// R5: register double-buffered fragments (hide LDSM->MMA latency),
//     fused amax / fused quant kernels (fewer launches; gemm into ncu window).
// ---------------------------------------------------------------------------

#define MT 16384
#define NT 4096
#define KT 4096

__device__ __align__(1024) int8_t g_qx[(size_t)MT * KT]; // 64 MiB scratch
__device__ __align__(1024) int8_t g_qw[(size_t)NT * KT]; // 16 MiB scratch
__device__ unsigned g_amax_x;
__device__ unsigned g_amax_w;

__device__ __forceinline__ uint32_t smem_to_u32(const void* smem_ptr) {
    uint32_t addr;
    asm("{ .reg .u64 tmp; cvta.to.shared.u64 tmp, %1; cvt.u32.u64 %0, tmp; }"
        : "=r"(addr) : "l"(smem_ptr));
    return addr;
}

// ---------------------------------------------------------------------------
// Pass 0: reset reduction state (graph replays must be deterministic)
// ---------------------------------------------------------------------------
__global__ void init_kernel() {
    if (threadIdx.x == 0) { g_amax_x = 0u; g_amax_w = 0u; }
}

// ---------------------------------------------------------------------------
// Pass 1 (fused): abs-max of x (blocks [0,XB)) and w (blocks [XB,XB+WB))
// ---------------------------------------------------------------------------
#define XB 2048
#define WB 512
__global__ void amax_fused_kernel(const float* __restrict__ x,
                                  const float* __restrict__ w) {
    __shared__ float red[8];
    int isw = (blockIdx.x >= XB);
    const float4* p4 = (const float4*)(isw ? w : x);
    int n4 = isw ? (NT * KT / 4) : (MT * KT / 4);
    int nb = isw ? WB : XB;
    int bid = isw ? (blockIdx.x - XB) : blockIdx.x;

    float m = 0.f;
    int stride = nb * blockDim.x;
    for (int i = bid * blockDim.x + threadIdx.x; i < n4; i += stride) {
        float4 v = p4[i];
        m = fmaxf(m, fmaxf(fmaxf(fabsf(v.x), fabsf(v.y)),
                           fmaxf(fabsf(v.z), fabsf(v.w))));
    }
    #pragma unroll
    for (int o = 16; o; o >>= 1) m = fmaxf(m, __shfl_xor_sync(0xffffffffu, m, o));
    if ((threadIdx.x & 31) == 0) red[threadIdx.x >> 5] = m;
    __syncthreads();
    if (threadIdx.x == 0) {
        float mm = red[0];
        for (int j = 1; j < (int)(blockDim.x >> 5); j++) mm = fmaxf(mm, red[j]);
        atomicMax(isw ? &g_amax_w : &g_amax_x, __float_as_uint(mm));
    }
}

// ---------------------------------------------------------------------------
// Pass 2 (fused): quantize x (blocks [0,QXB)) and w (blocks [QXB,QXB+QWB))
// ---------------------------------------------------------------------------
#define QXB 4096
#define QWB 1024
__device__ __forceinline__ int q1(float v, float inv_scale) {
    int q = __float2int_rn(v * inv_scale);   // round-half-even like jnp.round
    return max(-127, min(127, q));
}

__global__ void quant_fused_kernel(const float* __restrict__ x,
                                   const float* __restrict__ w) {
    int isw = (blockIdx.x >= QXB);
    float scale = fmaxf(__uint_as_float(isw ? g_amax_w : g_amax_x) * (1.f / 127.f),
                        1e-8f);
    float inv = 1.f / scale;
    const float4* in4 = (const float4*)(isw ? w : x);
    uint32_t* o4 = isw ? (uint32_t*)g_qw : (uint32_t*)g_qx;
    int n4 = isw ? (NT * KT / 4) : (MT * KT / 4);
    int nb = isw ? QWB : QXB;
    int bid = isw ? (blockIdx.x - QXB) : blockIdx.x;

    int stride = nb * blockDim.x;
    for (int i = bid * blockDim.x + threadIdx.x; i < n4; i += stride) {
        float4 v = in4[i];
        uint32_t u = (uint32_t)(q1(v.x, inv) & 0xff)
                   | ((uint32_t)(q1(v.y, inv) & 0xff) << 8)
                   | ((uint32_t)(q1(v.z, inv) & 0xff) << 16)
                   | ((uint32_t)(q1(v.w, inv) & 0xff) << 24);
        o4[i] = u;
    }
}

// ---------------------------------------------------------------------------
// Pass 3: int8 GEMM. Tile 128x128x128, 256 threads (2x4 warps, 64x32 / warp),
// 3-stage cp.async pipeline (96 KB smem, 2 CTA/SM), mma.m16n8k32.s8,
// register double-buffered fragments.
// ---------------------------------------------------------------------------
#define BM 128
#define BN 128
#define BK 128
#define STAGES 3
#define NITER (KT / BK)                  // 32
#define ASZ (BM * BK)                    // 16384 B
#define BSZ (BN * BK)                    // 16384 B
#define STAGE_BYTES (ASZ + BSZ)          // 32768 B
#define GEMM_SMEM (STAGES * STAGE_BYTES) // 98304 B

// 128B rows, 8 x 16B chunks; chunk' = chunk ^ (row&7): conflict-free for the
// 16B cp.async stores and for ldmatrix reads.
__device__ __forceinline__ uint32_t swz128(uint32_t row, uint32_t c) {
    return row * 128u + ((c ^ (row & 7u)) << 4);
}

#define CP16(dst, src) \
    asm volatile("cp.async.cg.shared.global [%0], [%1], 16;" :: "r"(dst), "l"(src))
#define CP_COMMIT() asm volatile("cp.async.commit_group;" ::: "memory")
#define CP_WAIT(n)  asm volatile("cp.async.wait_group %0;" :: "n"(n) : "memory")

#define LDSM_X4(r0, r1, r2, r3, a) \
    asm volatile("ldmatrix.sync.aligned.m8n8.x4.shared.b16 {%0,%1,%2,%3}, [%4];" \
        : "=r"(r0), "=r"(r1), "=r"(r2), "=r"(r3) : "r"(a))

#define MMA_S8(c, a, b0, b1) \
    asm volatile("mma.sync.aligned.m16n8k32.row.col.s32.s8.s8.s32 " \
        "{%0,%1,%2,%3}, {%4,%5,%6,%7}, {%8,%9}, {%0,%1,%2,%3};" \
        : "+r"((c)[0]), "+r"((c)[1]), "+r"((c)[2]), "+r"((c)[3]) \
        : "r"((a)[0]), "r"((a)[1]), "r"((a)[2]), "r"((a)[3]), "r"(b0), "r"(b1))

__global__ void __launch_bounds__(256, 2)
gemm_kernel(float* __restrict__ out, const float* __restrict__ bias) {
    extern __shared__ char smem[];
    uint32_t sb = smem_to_u32(smem);
    int tid = threadIdx.x, lane = tid & 31, w = tid >> 5;
    int wm = w & 1, wn = w >> 1;          // 2 x 4 warp grid
    int mtile = blockIdx.y, ntile = blockIdx.x;

    // cp.async constants: thread covers rows {r0,+32,+64,+96}, chunk cc.
    int r0 = tid >> 3, cc = tid & 7;
    const int8_t* gA = g_qx + ((size_t)(mtile * BM + r0)) * KT + cc * 16;
    const int8_t* gB = g_qw + ((size_t)(ntile * BN + r0)) * KT + cc * 16;
    uint32_t dA = swz128((uint32_t)r0, (uint32_t)cc);

    int acc[4][4][4];
    #pragma unroll
    for (int i = 0; i < 4; i++)
        #pragma unroll
        for (int j = 0; j < 4; j++)
            #pragma unroll
            for (int k = 0; k < 4; k++) acc[i][j][k] = 0;

    // ldmatrix stage-relative lane offsets for ks=0; ks toggles bits via ^(ks<<5)
    uint32_t a_row = (uint32_t)(wm * 64 + ((lane >> 3) & 1) * 8 + (lane & 7));
    uint32_t a_cb  = (uint32_t)((lane >> 4) & 1);
    uint32_t aoff[4];
    #pragma unroll
    for (int mt = 0; mt < 4; mt++) aoff[mt] = swz128(a_row + mt * 16, a_cb);

    uint32_t b_row = (uint32_t)(wn * 32 + ((lane >> 4) & 1) * 8 + (lane & 7));
    uint32_t b_cb  = (uint32_t)((lane >> 3) & 1);
    uint32_t boff[2];
    #pragma unroll
    for (int p = 0; p < 2; p++) boff[p] = swz128(b_row + p * 16, b_cb);

    // Prologue: fill stages 0..STAGES-2
    #pragma unroll
    for (int s = 0; s < STAGES - 1; s++) {
        uint32_t st = sb + (uint32_t)s * STAGE_BYTES;
        #pragma unroll
        for (int it = 0; it < 4; it++)
            CP16(st + dA + it * 4096u, gA + (size_t)it * 32 * KT + s * BK);
        #pragma unroll
        for (int it = 0; it < 4; it++)
            CP16(st + ASZ + dA + it * 4096u, gB + (size_t)it * 32 * KT + s * BK);
        CP_COMMIT();
    }

    uint32_t afr[2][4][4], bfr[2][2][4];   // double-buffered fragments

    for (int kc = 0; kc < NITER; kc++) {
        CP_WAIT(STAGES - 2);
        __syncthreads();

        int lc = kc + STAGES - 1;
        if (lc < NITER) {
            uint32_t st = sb + (uint32_t)(lc % STAGES) * STAGE_BYTES;
            #pragma unroll
            for (int it = 0; it < 4; it++)
                CP16(st + dA + it * 4096u, gA + (size_t)it * 32 * KT + lc * BK);
            #pragma unroll
            for (int it = 0; it < 4; it++)
                CP16(st + ASZ + dA + it * 4096u,
                     gB + (size_t)it * 32 * KT + lc * BK);
        }
        CP_COMMIT();

        uint32_t sA = sb + (uint32_t)(kc % STAGES) * STAGE_BYTES;
        uint32_t sB = sA + ASZ;

        // Preload ks=0 fragments into buffer 0
        #pragma unroll
        for (int mt = 0; mt < 4; mt++)
            LDSM_X4(afr[0][mt][0], afr[0][mt][1], afr[0][mt][2], afr[0][mt][3],
                    sA + aoff[mt]);
        #pragma unroll
        for (int p = 0; p < 2; p++)
            LDSM_X4(bfr[0][p][0], bfr[0][p][1], bfr[0][p][2], bfr[0][p][3],
                    sB + boff[p]);

        #pragma unroll
        for (int ks = 0; ks < 4; ks++) {
            int cur = ks & 1, nxt = cur ^ 1;
            if (ks < 3) {   // prefetch ks+1 BEFORE the MMAs of ks
                uint32_t x = (uint32_t)(ks + 1) << 5;
                #pragma unroll
                for (int mt = 0; mt < 4; mt++)
                    LDSM_X4(afr[nxt][mt][0], afr[nxt][mt][1],
                            afr[nxt][mt][2], afr[nxt][mt][3],
                            sA + (aoff[mt] ^ x));
                #pragma unroll
                for (int p = 0; p < 2; p++)
                    LDSM_X4(bfr[nxt][p][0], bfr[nxt][p][1],
                            bfr[nxt][p][2], bfr[nxt][p][3],
                            sB + (boff[p] ^ x));
            }
            #pragma unroll
            for (int mt = 0; mt < 4; mt++)
                #pragma unroll
                for (int nt = 0; nt < 4; nt++)
                    MMA_S8(acc[mt][nt], afr[cur][mt],
                           bfr[cur][nt >> 1][(nt & 1) * 2],
                           bfr[cur][nt >> 1][(nt & 1) * 2 + 1]);
        }
    }

    // Epilogue: float(acc) * (sx*sw) + bias
    float sx = fmaxf(__uint_as_float(g_amax_x) * (1.f / 127.f), 1e-8f);
    float sw = fmaxf(__uint_as_float(g_amax_w) * (1.f / 127.f), 1e-8f);
    float sc = sx * sw;

    int colbase = ntile * BN + wn * 32 + 2 * (lane & 3);
    int rowbase = mtile * BM + wm * 64 + (lane >> 2);

    float2 bv[4];
    #pragma unroll
    for (int nt = 0; nt < 4; nt++)
        bv[nt] = *reinterpret_cast<const float2*>(bias + colbase + nt * 8);

    #pragma unroll
    for (int mt = 0; mt < 4; mt++) {
        int r = rowbase + mt * 16;
        #pragma unroll
        for (int nt = 0; nt < 4; nt++) {
            int col = colbase + nt * 8;
            float2 v0, v1;
            v0.x = fmaf((float)acc[mt][nt][0], sc, bv[nt].x);
            v0.y = fmaf((float)acc[mt][nt][1], sc, bv[nt].y);
            v1.x = fmaf((float)acc[mt][nt][2], sc, bv[nt].x);
            v1.y = fmaf((float)acc[mt][nt][3], sc, bv[nt].y);
            *reinterpret_cast<float2*>(out + (size_t)r * NT + col) = v0;
            *reinterpret_cast<float2*>(out + (size_t)(r + 8) * NT + col) = v1;
        }
    }
}

// ---------------------------------------------------------------------------
// Launch (graph-capturable; no allocation, no sync)
// ---------------------------------------------------------------------------
extern "C" void kernel_launch(void* const* d_in, const int* in_sizes, int n_in,
                              void* d_out, int out_size) {
    const float* x = (const float*)d_in[0];
    const float* w = (const float*)d_in[1];
    const float* bias = (const float*)d_in[2];
    float* out = (float*)d_out;

    init_kernel<<<1, 32>>>();
    amax_fused_kernel<<<XB + WB, 256>>>(x, w);
    quant_fused_kernel<<<QXB + QWB, 256>>>(x, w);

    cudaFuncSetAttribute(gemm_kernel,
                         cudaFuncAttributeMaxDynamicSharedMemorySize, GEMM_SMEM);
    gemm_kernel<<<dim3(NT / BN, MT / BM), 256, GEMM_SMEM>>>(out, bias);
}

// round 9
// speedup vs baseline: 1.1651x; 1.1543x over previous
#include <cuda_runtime.h>
#include <cstdint>
#include <cstddef>

// ---------------------------------------------------------------------------
// out = fq(x) @ fq(W)^T + bias, fq = per-tensor symmetric int8 fake quant.
// Exact: out = (q_x @ q_w^T) * (s_x*s_w) + bias, int32 accumulation.
//
// R7: HYBRID GEMM. ncu shows legacy-IMMA tensor pipe 98.8% busy (~78 TOPS
// hard floor on sm_103; tcgen05 unavailable: harness PTX target lacks 'a').
// So split N-columns between tensor-pipe CTAs (mma.sync) and ALU-pipe CTAs
// (dp4a SIMT GEMM); both co-resident per SM -> two pipes run concurrently.
//   bx in [0,12):  dp4a path, columns [0,1536)
//   bx in [12,32): IMMA path, columns [1536,4096)
// ---------------------------------------------------------------------------

#define MT 16384
#define NT 4096
#define KT 4096

__device__ __align__(1024) int8_t g_qx[(size_t)MT * KT]; // 64 MiB scratch
__device__ __align__(1024) int8_t g_qw[(size_t)NT * KT]; // 16 MiB scratch
__device__ unsigned g_amax_x;
__device__ unsigned g_amax_w;

__device__ __forceinline__ uint32_t smem_to_u32(const void* smem_ptr) {
    uint32_t addr;
    asm("{ .reg .u64 tmp; cvta.to.shared.u64 tmp, %1; cvt.u32.u64 %0, tmp; }"
        : "=r"(addr) : "l"(smem_ptr));
    return addr;
}

// ---------------------------------------------------------------------------
// Pass 0: reset reduction state
// ---------------------------------------------------------------------------
__global__ void init_kernel() {
    if (threadIdx.x == 0) { g_amax_x = 0u; g_amax_w = 0u; }
}

// ---------------------------------------------------------------------------
// Pass 1 (fused): abs-max of x (blocks [0,XB)) and w (blocks [XB,XB+WB))
// ---------------------------------------------------------------------------
#define XB 2048
#define WB 512
__global__ void amax_fused_kernel(const float* __restrict__ x,
                                  const float* __restrict__ w) {
    __shared__ float red[8];
    int isw = (blockIdx.x >= XB);
    const float4* p4 = (const float4*)(isw ? w : x);
    int n4 = isw ? (NT * KT / 4) : (MT * KT / 4);
    int nb = isw ? WB : XB;
    int bid = isw ? (blockIdx.x - XB) : blockIdx.x;

    float m = 0.f;
    int stride = nb * blockDim.x;
    for (int i = bid * blockDim.x + threadIdx.x; i < n4; i += stride) {
        float4 v = p4[i];
        m = fmaxf(m, fmaxf(fmaxf(fabsf(v.x), fabsf(v.y)),
                           fmaxf(fabsf(v.z), fabsf(v.w))));
    }
    #pragma unroll
    for (int o = 16; o; o >>= 1) m = fmaxf(m, __shfl_xor_sync(0xffffffffu, m, o));
    if ((threadIdx.x & 31) == 0) red[threadIdx.x >> 5] = m;
    __syncthreads();
    if (threadIdx.x == 0) {
        float mm = red[0];
        for (int j = 1; j < (int)(blockDim.x >> 5); j++) mm = fmaxf(mm, red[j]);
        atomicMax(isw ? &g_amax_w : &g_amax_x, __float_as_uint(mm));
    }
}

// ---------------------------------------------------------------------------
// Pass 2 (fused): quantize x and w to int8
// ---------------------------------------------------------------------------
#define QXB 4096
#define QWB 1024
__device__ __forceinline__ int q1(float v, float inv_scale) {
    int q = __float2int_rn(v * inv_scale);   // round-half-even like jnp.round
    return max(-127, min(127, q));
}

__global__ void quant_fused_kernel(const float* __restrict__ x,
                                   const float* __restrict__ w) {
    int isw = (blockIdx.x >= QXB);
    float scale = fmaxf(__uint_as_float(isw ? g_amax_w : g_amax_x) * (1.f / 127.f),
                        1e-8f);
    float inv = 1.f / scale;
    const float4* in4 = (const float4*)(isw ? w : x);
    uint32_t* o4 = isw ? (uint32_t*)g_qw : (uint32_t*)g_qx;
    int n4 = isw ? (NT * KT / 4) : (MT * KT / 4);
    int nb = isw ? QWB : QXB;
    int bid = isw ? (blockIdx.x - QXB) : blockIdx.x;

    int stride = nb * blockDim.x;
    for (int i = bid * blockDim.x + threadIdx.x; i < n4; i += stride) {
        float4 v = in4[i];
        uint32_t u = (uint32_t)(q1(v.x, inv) & 0xff)
                   | ((uint32_t)(q1(v.y, inv) & 0xff) << 8)
                   | ((uint32_t)(q1(v.z, inv) & 0xff) << 16)
                   | ((uint32_t)(q1(v.w, inv) & 0xff) << 24);
        o4[i] = u;
    }
}

// ---------------------------------------------------------------------------
// Pass 3: hybrid GEMM, tile 128x128x128, 256 threads, 3-stage cp.async.
// ---------------------------------------------------------------------------
#define BM 128
#define BN 128
#define BK 128
#define STAGES 3
#define NITER (KT / BK)                  // 32
#define ASZ (BM * BK)                    // 16384 B
#define BSZ (BN * BK)                    // 16384 B
#define STAGE_BYTES (ASZ + BSZ)          // 32768 B
#define GEMM_SMEM (STAGES * STAGE_BYTES) // 98304 B
#define DPT 12                           // dp4a N-tiles (cols [0, 12*128))

// IMMA swizzle: 128B rows, chunk' = chunk ^ (row&7)
__device__ __forceinline__ uint32_t swz128(uint32_t row, uint32_t c) {
    return row * 128u + ((c ^ (row & 7u)) << 4);
}
// dp4a swizzle: chunk' = chunk ^ ((row ^ row>>3)&7) -- spreads stride-8 rows
__device__ __forceinline__ uint32_t swzdp(uint32_t row, uint32_t c) {
    return row * 128u + ((c ^ ((row ^ (row >> 3)) & 7u)) << 4);
}

#define CP16(dst, src) \
    asm volatile("cp.async.cg.shared.global [%0], [%1], 16;" :: "r"(dst), "l"(src))
#define CP_COMMIT() asm volatile("cp.async.commit_group;" ::: "memory")
#define CP_WAIT(n)  asm volatile("cp.async.wait_group %0;" :: "n"(n) : "memory")

#define LDSM_X4(r0, r1, r2, r3, a) \
    asm volatile("ldmatrix.sync.aligned.m8n8.x4.shared.b16 {%0,%1,%2,%3}, [%4];" \
        : "=r"(r0), "=r"(r1), "=r"(r2), "=r"(r3) : "r"(a))

#define MMA_S8(c, a, b0, b1) \
    asm volatile("mma.sync.aligned.m16n8k32.row.col.s32.s8.s8.s32 " \
        "{%0,%1,%2,%3}, {%4,%5,%6,%7}, {%8,%9}, {%0,%1,%2,%3};" \
        : "+r"((c)[0]), "+r"((c)[1]), "+r"((c)[2]), "+r"((c)[3]) \
        : "r"((a)[0]), "r"((a)[1]), "r"((a)[2]), "r"((a)[3]), "r"(b0), "r"(b1))

__global__ void __launch_bounds__(256, 2)
gemm_kernel(float* __restrict__ out, const float* __restrict__ bias) {
    extern __shared__ char smem[];
    uint32_t sb = smem_to_u32(smem);
    int tid = threadIdx.x, lane = tid & 31, w = tid >> 5;
    int mtile = blockIdx.y, bx = blockIdx.x;

    // Common cp.async thread mapping: rows {r0,+32,+64,+96}, 16B chunk cc.
    int r0 = tid >> 3, cc = tid & 7;
    const int8_t* gA = g_qx + ((size_t)(mtile * BM + r0)) * KT + cc * 16;
    const int8_t* gB = g_qw + ((size_t)(bx * BN + r0)) * KT + cc * 16;

    float sx = fmaxf(__uint_as_float(g_amax_x) * (1.f / 127.f), 1e-8f);
    float sw = fmaxf(__uint_as_float(g_amax_w) * (1.f / 127.f), 1e-8f);
    float sc = sx * sw;

    if (bx < DPT) {
        // ================= dp4a path (ALU pipe) ============================
        int ty = tid >> 4, tx = tid & 15;
        uint32_t tyk = (uint32_t)(ty & 7), txk = (uint32_t)(tx & 7);

        // store offsets (dp4a swizzle), per it
        uint32_t dstA[4];
        #pragma unroll
        for (int it = 0; it < 4; it++)
            dstA[it] = swzdp((uint32_t)(r0 + 32 * it), (uint32_t)cc);

        int acc[8][8];
        #pragma unroll
        for (int i = 0; i < 8; i++)
            #pragma unroll
            for (int j = 0; j < 8; j++) acc[i][j] = 0;

        #pragma unroll
        for (int s = 0; s < STAGES - 1; s++) {
            uint32_t st = sb + (uint32_t)s * STAGE_BYTES;
            #pragma unroll
            for (int it = 0; it < 4; it++)
                CP16(st + dstA[it], gA + (size_t)it * 32 * KT + s * BK);
            #pragma unroll
            for (int it = 0; it < 4; it++)
                CP16(st + ASZ + dstA[it], gB + (size_t)it * 32 * KT + s * BK);
            CP_COMMIT();
        }

        for (int kc = 0; kc < NITER; kc++) {
            CP_WAIT(STAGES - 2);
            __syncthreads();

            int lc = kc + STAGES - 1;
            if (lc < NITER) {
                uint32_t st = sb + (uint32_t)(lc % STAGES) * STAGE_BYTES;
                #pragma unroll
                for (int it = 0; it < 4; it++)
                    CP16(st + dstA[it], gA + (size_t)it * 32 * KT + lc * BK);
                #pragma unroll
                for (int it = 0; it < 4; it++)
                    CP16(st + ASZ + dstA[it], gB + (size_t)it * 32 * KT + lc * BK);
            }
            CP_COMMIT();

            const char* base = smem + (size_t)(kc % STAGES) * STAGE_BYTES;

            #pragma unroll
            for (int c = 0; c < 8; c++) {
                uint32_t ao[8], bo[8];
                #pragma unroll
                for (int i = 0; i < 8; i++)
                    ao[i] = (uint32_t)((ty * 8 + i) * 128)
                          + (((uint32_t)c ^ ((uint32_t)i ^ tyk)) << 4);
                #pragma unroll
                for (int j = 0; j < 8; j++)
                    bo[j] = (uint32_t)((tx * 8 + j) * 128)
                          + (((uint32_t)c ^ ((uint32_t)j ^ txk)) << 4);

                #pragma unroll
                for (int h = 0; h < 2; h++) {
                    uint2 a2[8];
                    #pragma unroll
                    for (int i = 0; i < 8; i++)
                        a2[i] = *(const uint2*)(base + ao[i] + 8 * h);
                    #pragma unroll
                    for (int j = 0; j < 8; j++) {
                        uint2 b2 = *(const uint2*)(base + ASZ + bo[j] + 8 * h);
                        #pragma unroll
                        for (int i = 0; i < 8; i++) {
                            acc[i][j] = __dp4a((int)a2[i].x, (int)b2.x, acc[i][j]);
                            acc[i][j] = __dp4a((int)a2[i].y, (int)b2.y, acc[i][j]);
                        }
                    }
                }
            }
        }

        // epilogue
        int grow = mtile * BM + ty * 8;
        int gcol = bx * BN + tx * 8;
        float4 bv0 = *reinterpret_cast<const float4*>(bias + gcol);
        float4 bv1 = *reinterpret_cast<const float4*>(bias + gcol + 4);
        #pragma unroll
        for (int i = 0; i < 8; i++) {
            float* orow = out + (size_t)(grow + i) * NT + gcol;
            float4 v0, v1;
            v0.x = fmaf((float)acc[i][0], sc, bv0.x);
            v0.y = fmaf((float)acc[i][1], sc, bv0.y);
            v0.z = fmaf((float)acc[i][2], sc, bv0.z);
            v0.w = fmaf((float)acc[i][3], sc, bv0.w);
            v1.x = fmaf((float)acc[i][4], sc, bv1.x);
            v1.y = fmaf((float)acc[i][5], sc, bv1.y);
            v1.z = fmaf((float)acc[i][6], sc, bv1.z);
            v1.w = fmaf((float)acc[i][7], sc, bv1.w);
            *reinterpret_cast<float4*>(orow) = v0;
            *reinterpret_cast<float4*>(orow + 4) = v1;
        }
    } else {
        // ================= IMMA path (tensor pipe) =========================
        int wm = w & 1, wn = w >> 1;          // 2 x 4 warp grid
        uint32_t dA = swz128((uint32_t)r0, (uint32_t)cc);

        int acc[4][4][4];
        #pragma unroll
        for (int i = 0; i < 4; i++)
            #pragma unroll
            for (int j = 0; j < 4; j++)
                #pragma unroll
                for (int k = 0; k < 4; k++) acc[i][j][k] = 0;

        uint32_t a_row = (uint32_t)(wm * 64 + ((lane >> 3) & 1) * 8 + (lane & 7));
        uint32_t a_cb  = (uint32_t)((lane >> 4) & 1);
        uint32_t aoff[4];
        #pragma unroll
        for (int mt = 0; mt < 4; mt++) aoff[mt] = swz128(a_row + mt * 16, a_cb);

        uint32_t b_row = (uint32_t)(wn * 32 + ((lane >> 4) & 1) * 8 + (lane & 7));
        uint32_t b_cb  = (uint32_t)((lane >> 3) & 1);
        uint32_t boff[2];
        #pragma unroll
        for (int p = 0; p < 2; p++) boff[p] = swz128(b_row + p * 16, b_cb);

        #pragma unroll
        for (int s = 0; s < STAGES - 1; s++) {
            uint32_t st = sb + (uint32_t)s * STAGE_BYTES;
            #pragma unroll
            for (int it = 0; it < 4; it++)
                CP16(st + dA + it * 4096u, gA + (size_t)it * 32 * KT + s * BK);
            #pragma unroll
            for (int it = 0; it < 4; it++)
                CP16(st + ASZ + dA + it * 4096u, gB + (size_t)it * 32 * KT + s * BK);
            CP_COMMIT();
        }

        uint32_t afr[2][4][4], bfr[2][2][4];

        for (int kc = 0; kc < NITER; kc++) {
            CP_WAIT(STAGES - 2);
            __syncthreads();

            int lc = kc + STAGES - 1;
            if (lc < NITER) {
                uint32_t st = sb + (uint32_t)(lc % STAGES) * STAGE_BYTES;
                #pragma unroll
                for (int it = 0; it < 4; it++)
                    CP16(st + dA + it * 4096u, gA + (size_t)it * 32 * KT + lc * BK);
                #pragma unroll
                for (int it = 0; it < 4; it++)
                    CP16(st + ASZ + dA + it * 4096u,
                         gB + (size_t)it * 32 * KT + lc * BK);
            }
            CP_COMMIT();

            uint32_t sA = sb + (uint32_t)(kc % STAGES) * STAGE_BYTES;
            uint32_t sB = sA + ASZ;

            #pragma unroll
            for (int mt = 0; mt < 4; mt++)
                LDSM_X4(afr[0][mt][0], afr[0][mt][1], afr[0][mt][2], afr[0][mt][3],
                        sA + aoff[mt]);
            #pragma unroll
            for (int p = 0; p < 2; p++)
                LDSM_X4(bfr[0][p][0], bfr[0][p][1], bfr[0][p][2], bfr[0][p][3],
                        sB + boff[p]);

            #pragma unroll
            for (int ks = 0; ks < 4; ks++) {
                int cur = ks & 1, nxt = cur ^ 1;
                if (ks < 3) {
                    uint32_t x = (uint32_t)(ks + 1) << 5;
                    #pragma unroll
                    for (int mt = 0; mt < 4; mt++)
                        LDSM_X4(afr[nxt][mt][0], afr[nxt][mt][1],
                                afr[nxt][mt][2], afr[nxt][mt][3],
                                sA + (aoff[mt] ^ x));
                    #pragma unroll
                    for (int p = 0; p < 2; p++)
                        LDSM_X4(bfr[nxt][p][0], bfr[nxt][p][1],
                                bfr[nxt][p][2], bfr[nxt][p][3],
                                sB + (boff[p] ^ x));
                }
                #pragma unroll
                for (int mt = 0; mt < 4; mt++)
                    #pragma unroll
                    for (int nt = 0; nt < 4; nt++)
                        MMA_S8(acc[mt][nt], afr[cur][mt],
                               bfr[cur][nt >> 1][(nt & 1) * 2],
                               bfr[cur][nt >> 1][(nt & 1) * 2 + 1]);
            }
        }

        int colbase = bx * BN + wn * 32 + 2 * (lane & 3);
        int rowbase = mtile * BM + wm * 64 + (lane >> 2);

        float2 bv[4];
        #pragma unroll
        for (int nt = 0; nt < 4; nt++)
            bv[nt] = *reinterpret_cast<const float2*>(bias + colbase + nt * 8);

        #pragma unroll
        for (int mt = 0; mt < 4; mt++) {
            int r = rowbase + mt * 16;
            #pragma unroll
            for (int nt = 0; nt < 4; nt++) {
                int col = colbase + nt * 8;
                float2 v0, v1;
                v0.x = fmaf((float)acc[mt][nt][0], sc, bv[nt].x);
                v0.y = fmaf((float)acc[mt][nt][1], sc, bv[nt].y);
                v1.x = fmaf((float)acc[mt][nt][2], sc, bv[nt].x);
                v1.y = fmaf((float)acc[mt][nt][3], sc, bv[nt].y);
                *reinterpret_cast<float2*>(out + (size_t)r * NT + col) = v0;
                *reinterpret_cast<float2*>(out + (size_t)(r + 8) * NT + col) = v1;
            }
        }
    }
}

// ---------------------------------------------------------------------------
// Launch (graph-capturable; no allocation, no sync)
// ---------------------------------------------------------------------------
extern "C" void kernel_launch(void* const* d_in, const int* in_sizes, int n_in,
                              void* d_out, int out_size) {
    const float* x = (const float*)d_in[0];
    const float* w = (const float*)d_in[1];
    const float* bias = (const float*)d_in[2];
    float* out = (float*)d_out;

    init_kernel<<<1, 32>>>();
    amax_fused_kernel<<<XB + WB, 256>>>(x, w);
    quant_fused_kernel<<<QXB + QWB, 256>>>(x, w);

    cudaFuncSetAttribute(gemm_kernel,
                         cudaFuncAttributeMaxDynamicSharedMemorySize, GEMM_SMEM);
    gemm_kernel<<<dim3(NT / BN, MT / BM), 256, GEMM_SMEM>>>(out, bias);
}

// round 10
// speedup vs baseline: 1.1825x; 1.0149x over previous
#include <cuda_runtime.h>
#include <cstdint>
#include <cstddef>

// ---------------------------------------------------------------------------
// out = fq(x) @ fq(W)^T + bias, fq = per-tensor symmetric int8 fake quant.
// Exact: out = (q_x @ q_w^T) * (s_x*s_w) + bias, int32 accumulation.
//
// Hybrid GEMM (R7): tensor-pipe CTAs (mma.sync, 98.8%-saturated alone) +
// ALU-pipe CTAs (dp4a SIMT), co-resident per SM.
// R9: rebalance DPT 12->10 (measured r_dp4a/r_imma = 0.44), dp4a shared loads
// widened to LDS.128 (half the issue slots).
//   bx in [0,10):  dp4a path, columns [0,1280)
//   bx in [10,32): IMMA path, columns [1280,4096)
// ---------------------------------------------------------------------------

#define MT 16384
#define NT 4096
#define KT 4096

__device__ __align__(1024) int8_t g_qx[(size_t)MT * KT]; // 64 MiB scratch
__device__ __align__(1024) int8_t g_qw[(size_t)NT * KT]; // 16 MiB scratch
__device__ unsigned g_amax_x;
__device__ unsigned g_amax_w;

__device__ __forceinline__ uint32_t smem_to_u32(const void* smem_ptr) {
    uint32_t addr;
    asm("{ .reg .u64 tmp; cvta.to.shared.u64 tmp, %1; cvt.u32.u64 %0, tmp; }"
        : "=r"(addr) : "l"(smem_ptr));
    return addr;
}

// ---------------------------------------------------------------------------
// Pass 0: reset reduction state
// ---------------------------------------------------------------------------
__global__ void init_kernel() {
    if (threadIdx.x == 0) { g_amax_x = 0u; g_amax_w = 0u; }
}

// ---------------------------------------------------------------------------
// Pass 1 (fused): abs-max of x (blocks [0,XB)) and w (blocks [XB,XB+WB))
// ---------------------------------------------------------------------------
#define XB 2048
#define WB 512
__global__ void amax_fused_kernel(const float* __restrict__ x,
                                  const float* __restrict__ w) {
    __shared__ float red[8];
    int isw = (blockIdx.x >= XB);
    const float4* p4 = (const float4*)(isw ? w : x);
    int n4 = isw ? (NT * KT / 4) : (MT * KT / 4);
    int nb = isw ? WB : XB;
    int bid = isw ? (blockIdx.x - XB) : blockIdx.x;

    float m = 0.f;
    int stride = nb * blockDim.x;
    for (int i = bid * blockDim.x + threadIdx.x; i < n4; i += stride) {
        float4 v = p4[i];
        m = fmaxf(m, fmaxf(fmaxf(fabsf(v.x), fabsf(v.y)),
                           fmaxf(fabsf(v.z), fabsf(v.w))));
    }
    #pragma unroll
    for (int o = 16; o; o >>= 1) m = fmaxf(m, __shfl_xor_sync(0xffffffffu, m, o));
    if ((threadIdx.x & 31) == 0) red[threadIdx.x >> 5] = m;
    __syncthreads();
    if (threadIdx.x == 0) {
        float mm = red[0];
        for (int j = 1; j < (int)(blockDim.x >> 5); j++) mm = fmaxf(mm, red[j]);
        atomicMax(isw ? &g_amax_w : &g_amax_x, __float_as_uint(mm));
    }
}

// ---------------------------------------------------------------------------
// Pass 2 (fused): quantize x and w to int8
// ---------------------------------------------------------------------------
#define QXB 4096
#define QWB 1024
__device__ __forceinline__ int q1(float v, float inv_scale) {
    int q = __float2int_rn(v * inv_scale);   // round-half-even like jnp.round
    return max(-127, min(127, q));
}

__global__ void quant_fused_kernel(const float* __restrict__ x,
                                   const float* __restrict__ w) {
    int isw = (blockIdx.x >= QXB);
    float scale = fmaxf(__uint_as_float(isw ? g_amax_w : g_amax_x) * (1.f / 127.f),
                        1e-8f);
    float inv = 1.f / scale;
    const float4* in4 = (const float4*)(isw ? w : x);
    uint32_t* o4 = isw ? (uint32_t*)g_qw : (uint32_t*)g_qx;
    int n4 = isw ? (NT * KT / 4) : (MT * KT / 4);
    int nb = isw ? QWB : QXB;
    int bid = isw ? (blockIdx.x - QXB) : blockIdx.x;

    int stride = nb * blockDim.x;
    for (int i = bid * blockDim.x + threadIdx.x; i < n4; i += stride) {
        float4 v = in4[i];
        uint32_t u = (uint32_t)(q1(v.x, inv) & 0xff)
                   | ((uint32_t)(q1(v.y, inv) & 0xff) << 8)
                   | ((uint32_t)(q1(v.z, inv) & 0xff) << 16)
                   | ((uint32_t)(q1(v.w, inv) & 0xff) << 24);
        o4[i] = u;
    }
}

// ---------------------------------------------------------------------------
// Pass 3: hybrid GEMM, tile 128x128x128, 256 threads, 3-stage cp.async.
// ---------------------------------------------------------------------------
#define BM 128
#define BN 128
#define BK 128
#define STAGES 3
#define NITER (KT / BK)                  // 32
#define ASZ (BM * BK)                    // 16384 B
#define BSZ (BN * BK)                    // 16384 B
#define STAGE_BYTES (ASZ + BSZ)          // 32768 B
#define GEMM_SMEM (STAGES * STAGE_BYTES) // 98304 B
#define DPT 10                           // dp4a N-tiles (cols [0, 10*128))

// IMMA swizzle: 128B rows, chunk' = chunk ^ (row&7)
__device__ __forceinline__ uint32_t swz128(uint32_t row, uint32_t c) {
    return row * 128u + ((c ^ (row & 7u)) << 4);
}
// dp4a swizzle: chunk' = chunk ^ ((row ^ row>>3)&7) -- spreads stride-8 rows
__device__ __forceinline__ uint32_t swzdp(uint32_t row, uint32_t c) {
    return row * 128u + ((c ^ ((row ^ (row >> 3)) & 7u)) << 4);
}

#define CP16(dst, src) \
    asm volatile("cp.async.cg.shared.global [%0], [%1], 16;" :: "r"(dst), "l"(src))
#define CP_COMMIT() asm volatile("cp.async.commit_group;" ::: "memory")
#define CP_WAIT(n)  asm volatile("cp.async.wait_group %0;" :: "n"(n) : "memory")

#define LDSM_X4(r0, r1, r2, r3, a) \
    asm volatile("ldmatrix.sync.aligned.m8n8.x4.shared.b16 {%0,%1,%2,%3}, [%4];" \
        : "=r"(r0), "=r"(r1), "=r"(r2), "=r"(r3) : "r"(a))

#define MMA_S8(c, a, b0, b1) \
    asm volatile("mma.sync.aligned.m16n8k32.row.col.s32.s8.s8.s32 " \
        "{%0,%1,%2,%3}, {%4,%5,%6,%7}, {%8,%9}, {%0,%1,%2,%3};" \
        : "+r"((c)[0]), "+r"((c)[1]), "+r"((c)[2]), "+r"((c)[3]) \
        : "r"((a)[0]), "r"((a)[1]), "r"((a)[2]), "r"((a)[3]), "r"(b0), "r"(b1))

__global__ void __launch_bounds__(256, 2)
gemm_kernel(float* __restrict__ out, const float* __restrict__ bias) {
    extern __shared__ char smem[];
    uint32_t sb = smem_to_u32(smem);
    int tid = threadIdx.x, lane = tid & 31, w = tid >> 5;
    int mtile = blockIdx.y, bx = blockIdx.x;

    // Common cp.async thread mapping: rows {r0,+32,+64,+96}, 16B chunk cc.
    int r0 = tid >> 3, cc = tid & 7;
    const int8_t* gA = g_qx + ((size_t)(mtile * BM + r0)) * KT + cc * 16;
    const int8_t* gB = g_qw + ((size_t)(bx * BN + r0)) * KT + cc * 16;

    float sx = fmaxf(__uint_as_float(g_amax_x) * (1.f / 127.f), 1e-8f);
    float sw = fmaxf(__uint_as_float(g_amax_w) * (1.f / 127.f), 1e-8f);
    float sc = sx * sw;

    if (bx < DPT) {
        // ================= dp4a path (ALU pipe) ============================
        int ty = tid >> 4, tx = tid & 15;
        uint32_t tyk = (uint32_t)(ty & 7), txk = (uint32_t)(tx & 7);

        uint32_t dstA[4];
        #pragma unroll
        for (int it = 0; it < 4; it++)
            dstA[it] = swzdp((uint32_t)(r0 + 32 * it), (uint32_t)cc);

        int acc[8][8];
        #pragma unroll
        for (int i = 0; i < 8; i++)
            #pragma unroll
            for (int j = 0; j < 8; j++) acc[i][j] = 0;

        #pragma unroll
        for (int s = 0; s < STAGES - 1; s++) {
            uint32_t st = sb + (uint32_t)s * STAGE_BYTES;
            #pragma unroll
            for (int it = 0; it < 4; it++)
                CP16(st + dstA[it], gA + (size_t)it * 32 * KT + s * BK);
            #pragma unroll
            for (int it = 0; it < 4; it++)
                CP16(st + ASZ + dstA[it], gB + (size_t)it * 32 * KT + s * BK);
            CP_COMMIT();
        }

        for (int kc = 0; kc < NITER; kc++) {
            CP_WAIT(STAGES - 2);
            __syncthreads();

            int lc = kc + STAGES - 1;
            if (lc < NITER) {
                uint32_t st = sb + (uint32_t)(lc % STAGES) * STAGE_BYTES;
                #pragma unroll
                for (int it = 0; it < 4; it++)
                    CP16(st + dstA[it], gA + (size_t)it * 32 * KT + lc * BK);
                #pragma unroll
                for (int it = 0; it < 4; it++)
                    CP16(st + ASZ + dstA[it], gB + (size_t)it * 32 * KT + lc * BK);
            }
            CP_COMMIT();

            const char* base = smem + (size_t)(kc % STAGES) * STAGE_BYTES;

            // Per 16B K-chunk c: two i-halves of 4 A-rows (LDS.128), B row
            // chunks re-read per half (LDS.128). 24 LDS.128 + 512 dp4a per c.
            #pragma unroll
            for (int c = 0; c < 8; c++) {
                #pragma unroll
                for (int ih = 0; ih < 2; ih++) {
                    uint4 a4[4];
                    #pragma unroll
                    for (int q = 0; q < 4; q++) {
                        int i = ih * 4 + q;
                        uint32_t ao = (uint32_t)((ty * 8 + i) * 128)
                            + (((uint32_t)c ^ ((uint32_t)i ^ tyk)) << 4);
                        a4[q] = *(const uint4*)(base + ao);
                    }
                    #pragma unroll
                    for (int j = 0; j < 8; j++) {
                        uint32_t bo = (uint32_t)((tx * 8 + j) * 128)
                            + (((uint32_t)c ^ ((uint32_t)j ^ txk)) << 4);
                        uint4 b4 = *(const uint4*)(base + ASZ + bo);
                        #pragma unroll
                        for (int q = 0; q < 4; q++) {
                            int i = ih * 4 + q;
                            acc[i][j] = __dp4a((int)a4[q].x, (int)b4.x, acc[i][j]);
                            acc[i][j] = __dp4a((int)a4[q].y, (int)b4.y, acc[i][j]);
                            acc[i][j] = __dp4a((int)a4[q].z, (int)b4.z, acc[i][j]);
                            acc[i][j] = __dp4a((int)a4[q].w, (int)b4.w, acc[i][j]);
                        }
                    }
                }
            }
        }

        // epilogue
        int grow = mtile * BM + ty * 8;
        int gcol = bx * BN + tx * 8;
        float4 bv0 = *reinterpret_cast<const float4*>(bias + gcol);
        float4 bv1 = *reinterpret_cast<const float4*>(bias + gcol + 4);
        #pragma unroll
        for (int i = 0; i < 8; i++) {
            float* orow = out + (size_t)(grow + i) * NT + gcol;
            float4 v0, v1;
            v0.x = fmaf((float)acc[i][0], sc, bv0.x);
            v0.y = fmaf((float)acc[i][1], sc, bv0.y);
            v0.z = fmaf((float)acc[i][2], sc, bv0.z);
            v0.w = fmaf((float)acc[i][3], sc, bv0.w);
            v1.x = fmaf((float)acc[i][4], sc, bv1.x);
            v1.y = fmaf((float)acc[i][5], sc, bv1.y);
            v1.z = fmaf((float)acc[i][6], sc, bv1.z);
            v1.w = fmaf((float)acc[i][7], sc, bv1.w);
            *reinterpret_cast<float4*>(orow) = v0;
            *reinterpret_cast<float4*>(orow + 4) = v1;
        }
    } else {
        // ================= IMMA path (tensor pipe) =========================
        int wm = w & 1, wn = w >> 1;          // 2 x 4 warp grid
        uint32_t dA = swz128((uint32_t)r0, (uint32_t)cc);

        int acc[4][4][4];
        #pragma unroll
        for (int i = 0; i < 4; i++)
            #pragma unroll
            for (int j = 0; j < 4; j++)
                #pragma unroll
                for (int k = 0; k < 4; k++) acc[i][j][k] = 0;

        uint32_t a_row = (uint32_t)(wm * 64 + ((lane >> 3) & 1) * 8 + (lane & 7));
        uint32_t a_cb  = (uint32_t)((lane >> 4) & 1);
        uint32_t aoff[4];
        #pragma unroll
        for (int mt = 0; mt < 4; mt++) aoff[mt] = swz128(a_row + mt * 16, a_cb);

        uint32_t b_row = (uint32_t)(wn * 32 + ((lane >> 4) & 1) * 8 + (lane & 7));
        uint32_t b_cb  = (uint32_t)((lane >> 3) & 1);
        uint32_t boff[2];
        #pragma unroll
        for (int p = 0; p < 2; p++) boff[p] = swz128(b_row + p * 16, b_cb);

        #pragma unroll
        for (int s = 0; s < STAGES - 1; s++) {
            uint32_t st = sb + (uint32_t)s * STAGE_BYTES;
            #pragma unroll
            for (int it = 0; it < 4; it++)
                CP16(st + dA + it * 4096u, gA + (size_t)it * 32 * KT + s * BK);
            #pragma unroll
            for (int it = 0; it < 4; it++)
                CP16(st + ASZ + dA + it * 4096u, gB + (size_t)it * 32 * KT + s * BK);
            CP_COMMIT();
        }

        uint32_t afr[2][4][4], bfr[2][2][4];

        for (int kc = 0; kc < NITER; kc++) {
            CP_WAIT(STAGES - 2);
            __syncthreads();

            int lc = kc + STAGES - 1;
            if (lc < NITER) {
                uint32_t st = sb + (uint32_t)(lc % STAGES) * STAGE_BYTES;
                #pragma unroll
                for (int it = 0; it < 4; it++)
                    CP16(st + dA + it * 4096u, gA + (size_t)it * 32 * KT + lc * BK);
                #pragma unroll
                for (int it = 0; it < 4; it++)
                    CP16(st + ASZ + dA + it * 4096u,
                         gB + (size_t)it * 32 * KT + lc * BK);
            }
            CP_COMMIT();

            uint32_t sA = sb + (uint32_t)(kc % STAGES) * STAGE_BYTES;
            uint32_t sB = sA + ASZ;

            #pragma unroll
            for (int mt = 0; mt < 4; mt++)
                LDSM_X4(afr[0][mt][0], afr[0][mt][1], afr[0][mt][2], afr[0][mt][3],
                        sA + aoff[mt]);
            #pragma unroll
            for (int p = 0; p < 2; p++)
                LDSM_X4(bfr[0][p][0], bfr[0][p][1], bfr[0][p][2], bfr[0][p][3],
                        sB + boff[p]);

            #pragma unroll
            for (int ks = 0; ks < 4; ks++) {
                int cur = ks & 1, nxt = cur ^ 1;
                if (ks < 3) {
                    uint32_t x = (uint32_t)(ks + 1) << 5;
                    #pragma unroll
                    for (int mt = 0; mt < 4; mt++)
                        LDSM_X4(afr[nxt][mt][0], afr[nxt][mt][1],
                                afr[nxt][mt][2], afr[nxt][mt][3],
                                sA + (aoff[mt] ^ x));
                    #pragma unroll
                    for (int p = 0; p < 2; p++)
                        LDSM_X4(bfr[nxt][p][0], bfr[nxt][p][1],
                                bfr[nxt][p][2], bfr[nxt][p][3],
                                sB + (boff[p] ^ x));
                }
                #pragma unroll
                for (int mt = 0; mt < 4; mt++)
                    #pragma unroll
                    for (int nt = 0; nt < 4; nt++)
                        MMA_S8(acc[mt][nt], afr[cur][mt],
                               bfr[cur][nt >> 1][(nt & 1) * 2],
                               bfr[cur][nt >> 1][(nt & 1) * 2 + 1]);
            }
        }

        int colbase = bx * BN + wn * 32 + 2 * (lane & 3);
        int rowbase = mtile * BM + wm * 64 + (lane >> 2);

        float2 bv[4];
        #pragma unroll
        for (int nt = 0; nt < 4; nt++)
            bv[nt] = *reinterpret_cast<const float2*>(bias + colbase + nt * 8);

        #pragma unroll
        for (int mt = 0; mt < 4; mt++) {
            int r = rowbase + mt * 16;
            #pragma unroll
            for (int nt = 0; nt < 4; nt++) {
                int col = colbase + nt * 8;
                float2 v0, v1;
                v0.x = fmaf((float)acc[mt][nt][0], sc, bv[nt].x);
                v0.y = fmaf((float)acc[mt][nt][1], sc, bv[nt].y);
                v1.x = fmaf((float)acc[mt][nt][2], sc, bv[nt].x);
                v1.y = fmaf((float)acc[mt][nt][3], sc, bv[nt].y);
                *reinterpret_cast<float2*>(out + (size_t)r * NT + col) = v0;
                *reinterpret_cast<float2*>(out + (size_t)(r + 8) * NT + col) = v1;
            }
        }
    }
}

// ---------------------------------------------------------------------------
// Launch (graph-capturable; no allocation, no sync)
// ---------------------------------------------------------------------------
extern "C" void kernel_launch(void* const* d_in, const int* in_sizes, int n_in,
                              void* d_out, int out_size) {
    const float* x = (const float*)d_in[0];
    const float* w = (const float*)d_in[1];
    const float* bias = (const float*)d_in[2];
    float* out = (float*)d_out;

    init_kernel<<<1, 32>>>();
    amax_fused_kernel<<<XB + WB, 256>>>(x, w);
    quant_fused_kernel<<<QXB + QWB, 256>>>(x, w);

    cudaFuncSetAttribute(gemm_kernel,
                         cudaFuncAttributeMaxDynamicSharedMemorySize, GEMM_SMEM);
    gemm_kernel<<<dim3(NT / BN, MT / BM), 256, GEMM_SMEM>>>(out, bias);
}